// round 1
// baseline (speedup 1.0000x reference)
#include <cuda_runtime.h>
#include <math.h>

#define BATCH 8
#define NCLS 3
#define H 384
#define W 384
#define HW (H*W)
#define NBC (BATCH*NCLS)
#define INF_F 1.0e6f

// Scratch (device globals; re-initialized on every kernel_launch)
__device__ float g_fg[NBC*HW];   // fwd dist then squared min dist along axis0, set = (t != c)
__device__ float g_bg[NBC*HW];   // same, set = (t == c)
__device__ float d_fg[NBC*HW];   // euclidean distance maps
__device__ float d_bg[NBC*HW];
__device__ unsigned g_maxfg[NBC];
__device__ unsigned g_maxbg[NBC];
__device__ int g_any[NBC];
__device__ double g_sum;

__global__ void k0_init() {
    int t = threadIdx.x;
    if (t < NBC) { g_maxfg[t] = 0u; g_maxbg[t] = 0u; g_any[t] = 0; }
    if (t == 0) g_sum = 0.0;
}

// Column scans: thread = (bc, j). Two passes over rows with unroll-8 prefetch.
__global__ void k1_colscan(const int* __restrict__ targets) {
    int tid = blockIdx.x * blockDim.x + threadIdx.x;
    if (tid >= NBC * W) return;
    int j  = tid % W;
    int bc = tid / W;
    int b = bc / NCLS, c = bc % NCLS;
    const int* tg = targets + b * HW + j;

    float ffg = INF_F, fbg = INF_F;
    bool any = false;
    // pass 1: top -> bottom, store forward distances
    for (int i0 = 0; i0 < H; i0 += 8) {
        int tv[8];
        #pragma unroll
        for (int k = 0; k < 8; k++) tv[k] = tg[(i0 + k) * W];
        #pragma unroll
        for (int k = 0; k < 8; k++) {
            bool mb = (tv[k] == c);
            any = any || mb;
            fbg = mb ? 0.0f : (fbg + 1.0f);
            ffg = (!mb) ? 0.0f : (ffg + 1.0f);
            int idx = bc * HW + (i0 + k) * W + j;
            g_bg[idx] = fbg;
            g_fg[idx] = ffg;
        }
    }
    if (any) atomicOr(&g_any[bc], 1);

    // pass 2: bottom -> top, min with backward, square, store
    float bfg = INF_F, bbg = INF_F;
    for (int i0 = H - 8; i0 >= 0; i0 -= 8) {
        int tv[8]; float vfg[8], vbg[8];
        #pragma unroll
        for (int k = 0; k < 8; k++) {
            int idx = bc * HW + (i0 + k) * W + j;
            tv[k]  = tg[(i0 + k) * W];
            vfg[k] = g_fg[idx];
            vbg[k] = g_bg[idx];
        }
        #pragma unroll
        for (int k = 7; k >= 0; k--) {
            bool mb = (tv[k] == c);
            bbg = mb ? 0.0f : (bbg + 1.0f);
            bfg = (!mb) ? 0.0f : (bfg + 1.0f);
            float gb = fminf(vbg[k], bbg);
            float gf = fminf(vfg[k], bfg);
            int idx = bc * HW + (i0 + k) * W + j;
            g_bg[idx] = gb * gb;
            g_fg[idx] = gf * gf;
        }
    }
}

// Row EDT: block = (row, map). Center-out min with warp-ballot early exit.
// Evaluates the exact reference expression g2[k] + (j-k)^2 in fp32.
__global__ void k2_rowedt() {
    __shared__ float sh[W];
    __shared__ float wmax[W / 32];
    int row = blockIdx.x;      // 0..H-1
    int m   = blockIdx.y;      // 0..2*NBC-1
    int bc  = m >> 1;
    int sel = m & 1;
    const float* __restrict__ src = sel ? g_bg : g_fg;
    float* __restrict__ dst       = sel ? d_bg : d_fg;
    unsigned* mx                  = sel ? g_maxbg : g_maxfg;

    int j = threadIdx.x;
    int base = bc * HW + row * W;
    sh[j] = src[base + j];
    __syncthreads();

    float best = sh[j];  // r = 0 term
    for (int r = 1; r < W; ++r) {
        float rr = (float)(r * r);
        if (!__any_sync(0xffffffffu, rr < best)) break;  // g2 >= 0: cannot improve
        int lo = j - r, hi = j + r;
        if (lo >= 0) best = fminf(best, sh[lo] + rr);
        if (hi < W)  best = fminf(best, sh[hi] + rr);
    }
    float d = sqrtf(best);
    dst[base + j] = d;

    // block max -> atomicMax on float bits (all values >= 0)
    float v = d;
    #pragma unroll
    for (int off = 16; off; off >>= 1)
        v = fmaxf(v, __shfl_xor_sync(0xffffffffu, v, off));
    if ((threadIdx.x & 31) == 0) wmax[threadIdx.x >> 5] = v;
    __syncthreads();
    if (threadIdx.x == 0) {
        float mm = wmax[0];
        #pragma unroll
        for (int k = 1; k < W / 32; k++) mm = fmaxf(mm, wmax[k]);
        atomicMax(mx + bc, __float_as_uint(mm));
    }
}

// Softmax + normalized SDF combine + double reduction
__global__ void k3_reduce(const float* __restrict__ logits) {
    int tid = blockIdx.x * blockDim.x + threadIdx.x;  // over BATCH*HW
    float acc = 0.0f;
    if (tid < BATCH * HW) {
        int b   = tid / HW;
        int pix = tid % HW;
        float l0 = logits[(b * 3 + 0) * HW + pix];
        float l1 = logits[(b * 3 + 1) * HW + pix];
        float l2 = logits[(b * 3 + 2) * HW + pix];
        float ml = fmaxf(l0, fmaxf(l1, l2));
        float e0 = expf(l0 - ml), e1 = expf(l1 - ml), e2 = expf(l2 - ml);
        float inv = 1.0f / (e0 + e1 + e2);
        float p[3] = {e0 * inv, e1 * inv, e2 * inv};
        #pragma unroll
        for (int c = 0; c < 3; c++) {
            int bc = b * 3 + c;
            float sdf = 0.0f;
            if (g_any[bc]) {
                float mfg = fmaxf(__uint_as_float(g_maxfg[bc]), 1e-12f);
                float mbg = fmaxf(__uint_as_float(g_maxbg[bc]), 1e-12f);
                int idx = bc * HW + pix;
                sdf = d_bg[idx] / mbg - d_fg[idx] / mfg;
            }
            acc += p[c] * sdf;
        }
    }
    // block reduction in double
    double dv = (double)acc;
    #pragma unroll
    for (int off = 16; off; off >>= 1)
        dv += __shfl_xor_sync(0xffffffffu, dv, off);
    __shared__ double ws[8];
    int lane = threadIdx.x & 31, w = threadIdx.x >> 5;
    if (lane == 0) ws[w] = dv;
    __syncthreads();
    if (threadIdx.x == 0) {
        double s = 0.0;
        int nw = blockDim.x / 32;
        for (int k = 0; k < nw; k++) s += ws[k];
        atomicAdd(&g_sum, s);
    }
}

__global__ void k4_final(float* out) {
    out[0] = (float)(g_sum / ((double)BATCH * HW * NCLS));
}

extern "C" void kernel_launch(void* const* d_in, const int* in_sizes, int n_in,
                              void* d_out, int out_size) {
    const float* logits  = (const float*)d_in[0];
    const int*   targets = (const int*)d_in[1];

    k0_init<<<1, 32>>>();
    k1_colscan<<<(NBC * W + 255) / 256, 256>>>(targets);
    dim3 g2(H, 2 * NBC);
    k2_rowedt<<<g2, W>>>();
    k3_reduce<<<(BATCH * HW + 255) / 256, 256>>>(logits);
    k4_final<<<1, 1>>>((float*)d_out);
}

// round 2
// speedup vs baseline: 2.1228x; 2.1228x over previous
#include <cuda_runtime.h>
#include <math.h>

#define BATCH 8
#define NCLS 3
#define H 384
#define W 384
#define HW (H*W)
#define NBC 24
#define JT 8
#define NWARP 12   // 384/32

// Scratch (device globals, fully overwritten each launch)
__device__ unsigned g_packed[BATCH*HW];   // 3x10-bit column distances per pixel
__device__ float g_psum_bg[NBC*H];
__device__ float g_psum_fg[NBC*H];
__device__ float g_pmax_bg[NBC*H];
__device__ float g_pmax_fg[NBC*H];

// ---------------------------------------------------------------------------
// k1: per-column 1D distance to nearest (t==c) pixel, all 3 classes.
// Row-parallel: block = (b, 8-column tile), thread = row. Warp shuffle
// max-scans over packed u16 pairs (__vmaxu2) give last/next true index.
// Distances clamped to 1023 (sentinel; provably never wins in the row EDT
// when the mask is nonempty), packed 3x10 bits -> u32.
// ---------------------------------------------------------------------------
__global__ void k1_colscan(const int* __restrict__ targets) {
    __shared__ unsigned wp[NWARP][16];
    const int i = threadIdx.x;          // row
    const int lane = i & 31, wid = i >> 5;
    const int b = blockIdx.y;
    const int j0 = blockIdx.x * JT;

    const int4* tp = (const int4*)(targets + b*HW + i*W + j0);
    int4 ta = tp[0], tb = tp[1];
    int t[8] = {ta.x, ta.y, ta.z, ta.w, tb.x, tb.y, tb.z, tb.w};

    unsigned f01[8], f2[8];
    const unsigned ip1 = (unsigned)(i + 1);
    #pragma unroll
    for (int jj = 0; jj < 8; jj++) {
        f01[jj] = (t[jj]==0 ? ip1 : 0u) | ((t[jj]==1 ? ip1 : 0u) << 16);
        f2 [jj] = (t[jj]==2 ? ip1 : 0u);
    }
    // forward (prefix) inclusive max-scan within warp
    #pragma unroll
    for (int off = 1; off < 32; off <<= 1) {
        #pragma unroll
        for (int jj = 0; jj < 8; jj++) {
            unsigned o1 = __shfl_up_sync(0xffffffffu, f01[jj], off);
            unsigned o2 = __shfl_up_sync(0xffffffffu, f2 [jj], off);
            if (lane >= off) { f01[jj] = __vmaxu2(f01[jj], o1); f2[jj] = max(f2[jj], o2); }
        }
    }
    if (lane == 31) {
        #pragma unroll
        for (int jj = 0; jj < 8; jj++) { wp[wid][jj] = f01[jj]; wp[wid][8+jj] = f2[jj]; }
    }
    __syncthreads();
    for (int w = 0; w < wid; w++) {
        #pragma unroll
        for (int jj = 0; jj < 8; jj++) {
            f01[jj] = __vmaxu2(f01[jj], wp[w][jj]);
            f2 [jj] = max(f2[jj], wp[w][8+jj]);
        }
    }
    // forward distances (0 at true pixel, i - lastIdx otherwise, 1023 if none)
    unsigned dfw01[8], dfw2[8];
    #pragma unroll
    for (int jj = 0; jj < 8; jj++) {
        unsigned s0 = f01[jj] & 0xffffu, s1 = f01[jj] >> 16, s2 = f2[jj];
        unsigned d0 = s0 ? (ip1 - s0) : 1023u;
        unsigned d1 = s1 ? (ip1 - s1) : 1023u;
        unsigned d2 = s2 ? (ip1 - s2) : 1023u;
        dfw01[jj] = d0 | (d1 << 16);
        dfw2 [jj] = d2;
    }
    __syncthreads();   // before reusing wp

    // backward (suffix) max-scan: val = (t==c) ? (H - i) : 0
    const unsigned hri = (unsigned)(H - i);
    #pragma unroll
    for (int jj = 0; jj < 8; jj++) {
        f01[jj] = (t[jj]==0 ? hri : 0u) | ((t[jj]==1 ? hri : 0u) << 16);
        f2 [jj] = (t[jj]==2 ? hri : 0u);
    }
    #pragma unroll
    for (int off = 1; off < 32; off <<= 1) {
        #pragma unroll
        for (int jj = 0; jj < 8; jj++) {
            unsigned o1 = __shfl_down_sync(0xffffffffu, f01[jj], off);
            unsigned o2 = __shfl_down_sync(0xffffffffu, f2 [jj], off);
            if (lane + off < 32) { f01[jj] = __vmaxu2(f01[jj], o1); f2[jj] = max(f2[jj], o2); }
        }
    }
    if (lane == 0) {
        #pragma unroll
        for (int jj = 0; jj < 8; jj++) { wp[wid][jj] = f01[jj]; wp[wid][8+jj] = f2[jj]; }
    }
    __syncthreads();
    for (int w = wid + 1; w < NWARP; w++) {
        #pragma unroll
        for (int jj = 0; jj < 8; jj++) {
            f01[jj] = __vmaxu2(f01[jj], wp[w][jj]);
            f2 [jj] = max(f2[jj], wp[w][8+jj]);
        }
    }
    // combine: g = min(fwd, bwd), pack 3x10 bits
    const unsigned base = (unsigned)(b*HW + i*W + j0);
    #pragma unroll
    for (int jj = 0; jj < 8; jj++) {
        unsigned S0 = f01[jj] & 0xffffu, S1 = f01[jj] >> 16, S2 = f2[jj];
        unsigned db0 = S0 ? ((unsigned)H - S0 - (unsigned)i) : 1023u;
        unsigned db1 = S1 ? ((unsigned)H - S1 - (unsigned)i) : 1023u;
        unsigned db2 = S2 ? ((unsigned)H - S2 - (unsigned)i) : 1023u;
        unsigned g0 = min(dfw01[jj] & 0xffffu, db0);
        unsigned g1 = min(dfw01[jj] >> 16,     db1);
        unsigned g2 = min(dfw2[jj],            db2);
        g_packed[base + jj] = g0 | (g1 << 10) | (g2 << 20);
    }
}

// ---------------------------------------------------------------------------
// k2: fused row EDT (3 bg classes, center-out with warp-ballot exit) +
// fg maps via d_fg(c) = min(d_bg(c'), d_bg(c'')) + softmax + per-(map,row)
// partial weighted sums and maxes. No distance maps ever hit global memory.
// ---------------------------------------------------------------------------
__global__ void k2_fused(const float* __restrict__ logits) {
    __shared__ float sh[3][W];
    __shared__ float red[NWARP][12];
    const int j = threadIdx.x;
    const int row = blockIdx.x, b = blockIdx.y;
    const int lane = j & 31, wid = j >> 5;

    unsigned gp = g_packed[b*HW + row*W + j];
    float q0 = (float)(gp & 1023u);
    float q1 = (float)((gp >> 10) & 1023u);
    float q2 = (float)((gp >> 20) & 1023u);
    sh[0][j] = q0*q0; sh[1][j] = q1*q1; sh[2][j] = q2*q2;
    __syncthreads();

    float d2[3];
    #pragma unroll
    for (int c = 0; c < 3; c++) {
        float best = sh[c][j];
        for (int r = 1; r < W; ++r) {
            float rr = (float)(r * r);
            if (!__any_sync(0xffffffffu, rr < best)) break;   // g2 >= 0
            int lo = j - r, hi = j + r;
            if (lo >= 0) best = fminf(best, sh[c][lo] + rr);
            if (hi < W)  best = fminf(best, sh[c][hi] + rr);
        }
        d2[c] = best;
    }
    float dbg[3], dfg[3];
    dbg[0] = sqrtf(d2[0]); dbg[1] = sqrtf(d2[1]); dbg[2] = sqrtf(d2[2]);
    dfg[0] = sqrtf(fminf(d2[1], d2[2]));
    dfg[1] = sqrtf(fminf(d2[0], d2[2]));
    dfg[2] = sqrtf(fminf(d2[0], d2[1]));

    // softmax over classes
    const float* lp = logits + (b*3)*HW + row*W + j;
    float l0 = lp[0], l1 = lp[HW], l2 = lp[2*HW];
    float m = fmaxf(l0, fmaxf(l1, l2));
    float e0 = expf(l0 - m), e1 = expf(l1 - m), e2 = expf(l2 - m);
    float inv = 1.0f / (e0 + e1 + e2);
    float p[3] = {e0*inv, e1*inv, e2*inv};

    float v[12];
    #pragma unroll
    for (int c = 0; c < 3; c++) {
        v[c]   = p[c] * dbg[c];
        v[3+c] = p[c] * dfg[c];
        v[6+c] = dbg[c];
        v[9+c] = dfg[c];
    }
    // warp reduce: s<6 sum, s>=6 max
    #pragma unroll
    for (int off = 16; off; off >>= 1) {
        #pragma unroll
        for (int s = 0; s < 6; s++)  v[s] += __shfl_xor_sync(0xffffffffu, v[s], off);
        #pragma unroll
        for (int s = 6; s < 12; s++) v[s] = fmaxf(v[s], __shfl_xor_sync(0xffffffffu, v[s], off));
    }
    if (lane == 0) {
        #pragma unroll
        for (int s = 0; s < 12; s++) red[wid][s] = v[s];
    }
    __syncthreads();
    if (threadIdx.x < 12) {
        int s = threadIdx.x;
        float acc = red[0][s];
        #pragma unroll
        for (int w = 1; w < NWARP; w++)
            acc = (s < 6) ? (acc + red[w][s]) : fmaxf(acc, red[w][s]);
        int c = s % 3;
        int idx = (b*3 + c) * H + row;
        int grp = s / 3;
        if      (grp == 0) g_psum_bg[idx] = acc;
        else if (grp == 1) g_psum_fg[idx] = acc;
        else if (grp == 2) g_pmax_bg[idx] = acc;
        else               g_pmax_fg[idx] = acc;
    }
}

// ---------------------------------------------------------------------------
// k3: final reduce. Warp per (b,c) map; gate = (Mbg < 600) <=> mask nonempty.
// ---------------------------------------------------------------------------
__global__ void k3_final(float* out) {
    const int lane = threadIdx.x & 31, bc = threadIdx.x >> 5;   // 24 warps
    double sbg = 0.0, sfg = 0.0;
    float mbg = 0.0f, mfg = 0.0f;
    for (int r = lane; r < H; r += 32) {
        sbg += (double)g_psum_bg[bc*H + r];
        sfg += (double)g_psum_fg[bc*H + r];
        mbg = fmaxf(mbg, g_pmax_bg[bc*H + r]);
        mfg = fmaxf(mfg, g_pmax_fg[bc*H + r]);
    }
    #pragma unroll
    for (int off = 16; off; off >>= 1) {
        sbg += __shfl_xor_sync(0xffffffffu, sbg, off);
        sfg += __shfl_xor_sync(0xffffffffu, sfg, off);
        mbg = fmaxf(mbg, __shfl_xor_sync(0xffffffffu, mbg, off));
        mfg = fmaxf(mfg, __shfl_xor_sync(0xffffffffu, mfg, off));
    }
    __shared__ double cs[24];
    if (lane == 0) {
        double contrib = 0.0;
        if (mbg < 600.0f) {   // mask nonempty (sentinel-clamped maps are >= 1023)
            contrib = sbg / (double)fmaxf(mbg, 1e-12f)
                    - sfg / (double)fmaxf(mfg, 1e-12f);
        }
        cs[bc] = contrib;
    }
    __syncthreads();
    if (threadIdx.x == 0) {
        double s = 0.0;
        #pragma unroll
        for (int k = 0; k < 24; k++) s += cs[k];
        out[0] = (float)(s / (24.0 * (double)HW));
    }
}

extern "C" void kernel_launch(void* const* d_in, const int* in_sizes, int n_in,
                              void* d_out, int out_size) {
    const float* logits  = (const float*)d_in[0];
    const int*   targets = (const int*)d_in[1];

    dim3 g1(W / JT, BATCH);
    k1_colscan<<<g1, H>>>(targets);
    dim3 g2(H, BATCH);
    k2_fused<<<g2, W>>>(logits);
    k3_final<<<1, 24 * 32>>>((float*)d_out);
}

// round 3
// speedup vs baseline: 2.5907x; 1.2204x over previous
#include <cuda_runtime.h>
#include <math.h>

#define BATCH 8
#define NCLS 3
#define H 384
#define W 384
#define HW (H*W)
#define NBC 24
#define JT 8
#define NWARP 12   // 384/32

// Scratch (device globals, fully overwritten each launch)
__device__ unsigned g_packed[BATCH*HW];   // 3x10-bit column distances per pixel
__device__ float g_psum_bg[NBC*H];
__device__ float g_psum_fg[NBC*H];
__device__ float g_pmax_bg[NBC*H];
__device__ float g_pmax_fg[NBC*H];

// ---------------------------------------------------------------------------
// k1: per-column 1D distance to nearest (t==c) pixel, all 3 classes, via
// ballot bitmasks. Block = (8-col tile, b), thread = row. One ballot per
// (col,class) gives 32 rows' mask; 12 warps share via smem. Nearest set bit
// = AND + clz/ffs (O(1), rare fallback walk). Distances clamped to 1023
// (sentinel), packed 3x10 bits -> u32, stored as uint4.
// ---------------------------------------------------------------------------
__global__ void __launch_bounds__(384) k1_colscan(const int* __restrict__ targets) {
    __shared__ unsigned sm[NWARP][24];   // [word(row/32)][jj*3+c]
    const int i = threadIdx.x;           // row
    const int lane = i & 31, w = i >> 5;
    const int b = blockIdx.y;
    const int j0 = blockIdx.x * JT;

    const int4* tp = (const int4*)(targets + b*HW + i*W + j0);
    int4 ta = tp[0], tb = tp[1];
    int t[8] = {ta.x, ta.y, ta.z, ta.w, tb.x, tb.y, tb.z, tb.w};

    unsigned bal[24];
    #pragma unroll
    for (int jj = 0; jj < 8; jj++) {
        #pragma unroll
        for (int c = 0; c < 3; c++)
            bal[jj*3 + c] = __ballot_sync(0xffffffffu, t[jj] == c);
    }
    if (lane == 0) {
        uint4* sp = (uint4*)sm[w];
        sp[0] = make_uint4(bal[0],  bal[1],  bal[2],  bal[3]);
        sp[1] = make_uint4(bal[4],  bal[5],  bal[6],  bal[7]);
        sp[2] = make_uint4(bal[8],  bal[9],  bal[10], bal[11]);
        sp[3] = make_uint4(bal[12], bal[13], bal[14], bal[15]);
        sp[4] = make_uint4(bal[16], bal[17], bal[18], bal[19]);
        sp[5] = make_uint4(bal[20], bal[21], bal[22], bal[23]);
    }
    __syncthreads();

    const unsigned lowmask = 0xffffffffu >> (31 - lane);  // bits 0..lane
    const unsigned himask  = 0xffffffffu << lane;         // bits lane..31
    unsigned outp[8];
    #pragma unroll
    for (int jj = 0; jj < 8; jj++) {
        unsigned gp = 0;
        #pragma unroll
        for (int c = 0; c < 3; c++) {
            const int s = jj*3 + c;
            // fwd: nearest set bit at row <= i
            unsigned mlo = sm[w][s] & lowmask;
            int dfw = 1023;
            if (mlo) dfw = lane - (31 - __clz(mlo));
            else {
                for (int w2 = w - 1; w2 >= 0; --w2) {
                    unsigned m = sm[w2][s];
                    if (m) { dfw = lane + ((w - w2) << 5) - (31 - __clz(m)); break; }
                }
            }
            // bwd: nearest set bit at row >= i
            unsigned mhi = sm[w][s] & himask;
            int dbw = 1023;
            if (mhi) dbw = (__ffs(mhi) - 1) - lane;
            else {
                for (int w2 = w + 1; w2 < NWARP; ++w2) {
                    unsigned m = sm[w2][s];
                    if (m) { dbw = ((w2 - w) << 5) + (__ffs(m) - 1) - lane; break; }
                }
            }
            unsigned g = (unsigned)min(min(dfw, dbw), 1023);
            gp |= g << (10 * c);
        }
        outp[jj] = gp;
    }
    uint4* op = (uint4*)(g_packed + b*HW + i*W + j0);
    op[0] = make_uint4(outp[0], outp[1], outp[2], outp[3]);
    op[1] = make_uint4(outp[4], outp[5], outp[6], outp[7]);
}

// ---------------------------------------------------------------------------
// k2: fused row EDT (per-pixel early-exit: while r^2 < best, exact since
// terms >= r^2) + fg via min of other classes' bg d2 + softmax + per-(map,row)
// partial weighted sums / maxes. Maxes reduced with redux.sync on d2 bits.
// ---------------------------------------------------------------------------
__global__ void __launch_bounds__(384) k2_fused(const float* __restrict__ logits) {
    __shared__ float sh[3][W];
    __shared__ float red[NWARP][12];
    const int j = threadIdx.x;
    const int row = blockIdx.x, b = blockIdx.y;
    const int lane = j & 31, wid = j >> 5;

    unsigned gp = g_packed[b*HW + row*W + j];
    float q0 = (float)(gp & 1023u);
    float q1 = (float)((gp >> 10) & 1023u);
    float q2 = (float)((gp >> 20) & 1023u);
    sh[0][j] = q0*q0; sh[1][j] = q1*q1; sh[2][j] = q2*q2;
    __syncthreads();

    float d2[3];
    #pragma unroll
    for (int c = 0; c < 3; c++) {
        float best = sh[c][j];
        float rf = 1.0f;
        int r = 1;
        while (rf * rf < best) {
            float rr = rf * rf;
            int lo = j - r, hi = j + r;
            if (lo >= 0) best = fminf(best, sh[c][lo] + rr);
            if (hi < W)  best = fminf(best, sh[c][hi] + rr);
            r++; rf += 1.0f;
        }
        d2[c] = best;
    }
    float d2fg[3];
    d2fg[0] = fminf(d2[1], d2[2]);
    d2fg[1] = fminf(d2[0], d2[2]);
    d2fg[2] = fminf(d2[0], d2[1]);
    float dbg[3] = {sqrtf(d2[0]), sqrtf(d2[1]), sqrtf(d2[2])};
    float dfg[3] = {sqrtf(d2fg[0]), sqrtf(d2fg[1]), sqrtf(d2fg[2])};

    // softmax over classes
    const float* lp = logits + (b*3)*HW + row*W + j;
    float l0 = lp[0], l1 = lp[HW], l2 = lp[2*HW];
    float m = fmaxf(l0, fmaxf(l1, l2));
    float e0 = expf(l0 - m), e1 = expf(l1 - m), e2 = expf(l2 - m);
    float inv = 1.0f / (e0 + e1 + e2);
    float p[3] = {e0*inv, e1*inv, e2*inv};

    // warp reduce: 6 sums via shuffles, 6 maxes via redux on d2 bits
    float v[6];
    #pragma unroll
    for (int c = 0; c < 3; c++) { v[c] = p[c]*dbg[c]; v[3+c] = p[c]*dfg[c]; }
    #pragma unroll
    for (int off = 16; off; off >>= 1) {
        #pragma unroll
        for (int s = 0; s < 6; s++) v[s] += __shfl_xor_sync(0xffffffffu, v[s], off);
    }
    unsigned mxb[3], mxf[3];
    #pragma unroll
    for (int c = 0; c < 3; c++) {
        mxb[c] = __reduce_max_sync(0xffffffffu, __float_as_uint(d2[c]));
        mxf[c] = __reduce_max_sync(0xffffffffu, __float_as_uint(d2fg[c]));
    }
    if (lane == 0) {
        #pragma unroll
        for (int s = 0; s < 6; s++) red[wid][s] = v[s];
        #pragma unroll
        for (int c = 0; c < 3; c++) {
            red[wid][6 + c] = __uint_as_float(mxb[c]);
            red[wid][9 + c] = __uint_as_float(mxf[c]);
        }
    }
    __syncthreads();
    if (threadIdx.x < 12) {
        int s = threadIdx.x;
        float acc = red[0][s];
        #pragma unroll
        for (int ww = 1; ww < NWARP; ww++)
            acc = (s < 6) ? (acc + red[ww][s]) : fmaxf(acc, red[ww][s]);  // positive floats: fmax == u32 max
        int c = s % 3;
        int idx = (b*3 + c) * H + row;
        int grp = s / 3;
        if      (grp == 0) g_psum_bg[idx] = acc;
        else if (grp == 1) g_psum_fg[idx] = acc;
        else if (grp == 2) g_pmax_bg[idx] = sqrtf(acc);   // sqrt(max d2) == max d
        else               g_pmax_fg[idx] = sqrtf(acc);
    }
}

// ---------------------------------------------------------------------------
// k3: final reduce. Warp per (b,c) map; gate = (Mbg < 600) <=> mask nonempty.
// ---------------------------------------------------------------------------
__global__ void k3_final(float* out) {
    const int lane = threadIdx.x & 31, bc = threadIdx.x >> 5;   // 24 warps
    double sbg = 0.0, sfg = 0.0;
    float mbg = 0.0f, mfg = 0.0f;
    for (int r = lane; r < H; r += 32) {
        sbg += (double)g_psum_bg[bc*H + r];
        sfg += (double)g_psum_fg[bc*H + r];
        mbg = fmaxf(mbg, g_pmax_bg[bc*H + r]);
        mfg = fmaxf(mfg, g_pmax_fg[bc*H + r]);
    }
    #pragma unroll
    for (int off = 16; off; off >>= 1) {
        sbg += __shfl_xor_sync(0xffffffffu, sbg, off);
        sfg += __shfl_xor_sync(0xffffffffu, sfg, off);
        mbg = fmaxf(mbg, __shfl_xor_sync(0xffffffffu, mbg, off));
        mfg = fmaxf(mfg, __shfl_xor_sync(0xffffffffu, mfg, off));
    }
    __shared__ double cs[24];
    if (lane == 0) {
        double contrib = 0.0;
        if (mbg < 600.0f) {   // mask nonempty (sentinel-clamped maps are >= 1023)
            contrib = sbg / (double)fmaxf(mbg, 1e-12f)
                    - sfg / (double)fmaxf(mfg, 1e-12f);
        }
        cs[bc] = contrib;
    }
    __syncthreads();
    if (threadIdx.x == 0) {
        double s = 0.0;
        #pragma unroll
        for (int k = 0; k < 24; k++) s += cs[k];
        out[0] = (float)(s / (24.0 * (double)HW));
    }
}

extern "C" void kernel_launch(void* const* d_in, const int* in_sizes, int n_in,
                              void* d_out, int out_size) {
    const float* logits  = (const float*)d_in[0];
    const int*   targets = (const int*)d_in[1];

    dim3 g1(W / JT, BATCH);
    k1_colscan<<<g1, H>>>(targets);
    dim3 g2(H, BATCH);
    k2_fused<<<g2, W>>>(logits);
    k3_final<<<1, 24 * 32>>>((float*)d_out);
}

// round 4
// speedup vs baseline: 3.3033x; 1.2751x over previous
#include <cuda_runtime.h>
#include <math.h>

#define BATCH 8
#define NCLS 3
#define H 384
#define W 384
#define HW (H*W)
#define NBC 24
#define JT 8
#define NWARP 12   // 384/32
#define R 8        // rows per k2 block
#define RG (H/R)   // 48 row-groups
#define SENT2 1046529.0f   // 1023^2

// Scratch (device globals, fully overwritten each launch)
__device__ unsigned g_packed[BATCH*HW];   // 3x10-bit column distances per pixel
__device__ float g_psum_bg[NBC*RG];
__device__ float g_psum_fg[NBC*RG];
__device__ float g_pmax_bg[NBC*RG];
__device__ float g_pmax_fg[NBC*RG];

// ---------------------------------------------------------------------------
// k1: per-column 1D distance to nearest (t==c) pixel, all 3 classes, via
// ballot bitmasks. Block = (8-col tile, b), thread = row. Class-2 mask is
// ~(m0|m1) (targets in {0,1,2}). Nearest set bit = AND + clz/ffs with rare
// fallback walk. Distances clamped to 1023 (sentinel), packed 3x10 bits.
// ---------------------------------------------------------------------------
__global__ void __launch_bounds__(384) k1_colscan(const int* __restrict__ targets) {
    __shared__ unsigned sm[NWARP][24];   // [word(row/32)][jj*3+c]
    const int i = threadIdx.x;           // row
    const int lane = i & 31, w = i >> 5;
    const int b = blockIdx.y;
    const int j0 = blockIdx.x * JT;

    const int4* tp = (const int4*)(targets + b*HW + i*W + j0);
    int4 ta = tp[0], tb = tp[1];
    int t[8] = {ta.x, ta.y, ta.z, ta.w, tb.x, tb.y, tb.z, tb.w};

    unsigned bal[24];
    #pragma unroll
    for (int jj = 0; jj < 8; jj++) {
        unsigned b0 = __ballot_sync(0xffffffffu, t[jj] == 0);
        unsigned b1 = __ballot_sync(0xffffffffu, t[jj] == 1);
        bal[jj*3+0] = b0;
        bal[jj*3+1] = b1;
        bal[jj*3+2] = ~(b0 | b1);
    }
    if (lane == 0) {
        uint4* sp = (uint4*)sm[w];
        sp[0] = make_uint4(bal[0],  bal[1],  bal[2],  bal[3]);
        sp[1] = make_uint4(bal[4],  bal[5],  bal[6],  bal[7]);
        sp[2] = make_uint4(bal[8],  bal[9],  bal[10], bal[11]);
        sp[3] = make_uint4(bal[12], bal[13], bal[14], bal[15]);
        sp[4] = make_uint4(bal[16], bal[17], bal[18], bal[19]);
        sp[5] = make_uint4(bal[20], bal[21], bal[22], bal[23]);
    }
    __syncthreads();

    const unsigned lowmask = 0xffffffffu >> (31 - lane);  // bits 0..lane
    const unsigned himask  = 0xffffffffu << lane;         // bits lane..31
    unsigned outp[8];
    #pragma unroll
    for (int jj = 0; jj < 8; jj++) {
        unsigned gp = 0;
        #pragma unroll
        for (int c = 0; c < 3; c++) {
            const int s = jj*3 + c;
            unsigned mlo = sm[w][s] & lowmask;
            int dfw = 1023;
            if (mlo) dfw = lane - (31 - __clz(mlo));
            else {
                for (int w2 = w - 1; w2 >= 0; --w2) {
                    unsigned m = sm[w2][s];
                    if (m) { dfw = lane + ((w - w2) << 5) - (31 - __clz(m)); break; }
                }
            }
            unsigned mhi = sm[w][s] & himask;
            int dbw = 1023;
            if (mhi) dbw = (__ffs(mhi) - 1) - lane;
            else {
                for (int w2 = w + 1; w2 < NWARP; ++w2) {
                    unsigned m = sm[w2][s];
                    if (m) { dbw = ((w2 - w) << 5) + (__ffs(m) - 1) - lane; break; }
                }
            }
            unsigned g = (unsigned)min(dfw, dbw);
            gp |= g << (10 * c);
        }
        outp[jj] = gp;
    }
    uint4* op = (uint4*)(g_packed + b*HW + i*W + j0);
    op[0] = make_uint4(outp[0], outp[1], outp[2], outp[3]);
    op[1] = make_uint4(outp[4], outp[5], outp[6], outp[7]);
}

// ---------------------------------------------------------------------------
// k2: fused row EDT + softmax + partial reductions, R=8 rows per block.
// Double-buffered, sentinel-padded smem (pads never win: 1023^2 > 2*383^2).
// Merged 3-class EDT loop with live per-pixel exit (exact: terms >= r^2).
// Per-thread accumulators across rows; one reduction per block.
// ---------------------------------------------------------------------------
__global__ void __launch_bounds__(384) k2_fused(const float* __restrict__ logits) {
    __shared__ float sh[2][3][3*W];   // [buf][class][pad W | data W | pad W]
    __shared__ float red[NWARP][12];
    const int j = threadIdx.x;
    const int rg = blockIdx.x, b = blockIdx.y;
    const int row0 = rg * R;
    const int lane = j & 31, wid = j >> 5;

    // sentinel pads (written once; never overwritten)
    #pragma unroll
    for (int buf = 0; buf < 2; buf++)
        #pragma unroll
        for (int c = 0; c < 3; c++) {
            sh[buf][c][j]       = SENT2;
            sh[buf][c][2*W + j] = SENT2;
        }

    float accs[6] = {0,0,0,0,0,0};      // p*dbg, p*dfg per class
    float accm[6] = {0,0,0,0,0,0};      // max d2 bg, max d2 fg per class

    unsigned cur = g_packed[b*HW + row0*W + j];
    int buf = 0;

    for (int ri = 0; ri < R; ri++) {
        const int row = row0 + ri;
        float q0 = (float)(cur & 1023u);
        float q1 = (float)((cur >> 10) & 1023u);
        float q2 = (float)((cur >> 20) & 1023u);
        sh[buf][0][W + j] = q0*q0;
        sh[buf][1][W + j] = q1*q1;
        sh[buf][2][W + j] = q2*q2;
        __syncthreads();
        if (ri + 1 < R) cur = g_packed[b*HW + (row+1)*W + j];

        const float* s0 = &sh[buf][0][W];
        const float* s1 = &sh[buf][1][W];
        const float* s2 = &sh[buf][2][W];
        float b0 = s0[j], b1 = s1[j], b2 = s2[j];
        float bestmax = fmaxf(b0, fmaxf(b1, b2));
        float rf = 1.0f;
        int r = 1;
        while (rf*rf < bestmax && r < W) {
            float rr = rf*rf;
            b0 = fminf(b0, fminf(s0[j-r], s0[j+r]) + rr);
            b1 = fminf(b1, fminf(s1[j-r], s1[j+r]) + rr);
            b2 = fminf(b2, fminf(s2[j-r], s2[j+r]) + rr);
            bestmax = fmaxf(b0, fmaxf(b1, b2));
            r++; rf += 1.0f;
        }
        float f0 = fminf(b1, b2);   // fg d2 = min of other classes' bg d2
        float f1 = fminf(b0, b2);
        float f2 = fminf(b0, b1);

        // fast softmax (no max-sub: |logits| small; __expf err ~2e-7)
        const float* lp = logits + (b*3)*HW + row*W + j;
        float e0 = __expf(lp[0]), e1 = __expf(lp[HW]), e2 = __expf(lp[2*HW]);
        float inv = __fdividef(1.0f, e0 + e1 + e2);

        accs[0] += e0*inv * sqrtf(b0);
        accs[1] += e1*inv * sqrtf(b1);
        accs[2] += e2*inv * sqrtf(b2);
        accs[3] += e0*inv * sqrtf(f0);
        accs[4] += e1*inv * sqrtf(f1);
        accs[5] += e2*inv * sqrtf(f2);
        accm[0] = fmaxf(accm[0], b0);
        accm[1] = fmaxf(accm[1], b1);
        accm[2] = fmaxf(accm[2], b2);
        accm[3] = fmaxf(accm[3], f0);
        accm[4] = fmaxf(accm[4], f1);
        accm[5] = fmaxf(accm[5], f2);
        buf ^= 1;
    }

    // warp reduce: 6 sums via shuffles, 6 maxes via redux on positive bits
    #pragma unroll
    for (int off = 16; off; off >>= 1) {
        #pragma unroll
        for (int s = 0; s < 6; s++) accs[s] += __shfl_xor_sync(0xffffffffu, accs[s], off);
    }
    #pragma unroll
    for (int s = 0; s < 6; s++)
        accm[s] = __uint_as_float(__reduce_max_sync(0xffffffffu, __float_as_uint(accm[s])));

    if (lane == 0) {
        #pragma unroll
        for (int s = 0; s < 6; s++) { red[wid][s] = accs[s]; red[wid][6+s] = accm[s]; }
    }
    __syncthreads();
    if (threadIdx.x < 12) {
        int s = threadIdx.x;
        float acc = red[0][s];
        #pragma unroll
        for (int ww = 1; ww < NWARP; ww++)
            acc = (s < 6) ? (acc + red[ww][s]) : fmaxf(acc, red[ww][s]);
        int c = s % 3;
        int idx = (b*3 + c) * RG + rg;
        int grp = s / 3;
        if      (grp == 0) g_psum_bg[idx] = acc;
        else if (grp == 1) g_psum_fg[idx] = acc;
        else if (grp == 2) g_pmax_bg[idx] = sqrtf(acc);   // sqrt(max d2) == max d
        else               g_pmax_fg[idx] = sqrtf(acc);
    }
}

// ---------------------------------------------------------------------------
// k3: final reduce. Warp per (b,c) map; gate = (Mbg < 600) <=> mask nonempty.
// ---------------------------------------------------------------------------
__global__ void k3_final(float* out) {
    const int lane = threadIdx.x & 31, bc = threadIdx.x >> 5;   // 24 warps
    double sbg = 0.0, sfg = 0.0;
    float mbg = 0.0f, mfg = 0.0f;
    for (int r = lane; r < RG; r += 32) {
        sbg += (double)g_psum_bg[bc*RG + r];
        sfg += (double)g_psum_fg[bc*RG + r];
        mbg = fmaxf(mbg, g_pmax_bg[bc*RG + r]);
        mfg = fmaxf(mfg, g_pmax_fg[bc*RG + r]);
    }
    #pragma unroll
    for (int off = 16; off; off >>= 1) {
        sbg += __shfl_xor_sync(0xffffffffu, sbg, off);
        sfg += __shfl_xor_sync(0xffffffffu, sfg, off);
        mbg = fmaxf(mbg, __shfl_xor_sync(0xffffffffu, mbg, off));
        mfg = fmaxf(mfg, __shfl_xor_sync(0xffffffffu, mfg, off));
    }
    __shared__ double cs[24];
    if (lane == 0) {
        double contrib = 0.0;
        if (mbg < 600.0f) {   // mask nonempty (empty-map sentinel d >= 1023)
            contrib = sbg / (double)fmaxf(mbg, 1e-12f)
                    - sfg / (double)fmaxf(mfg, 1e-12f);
        }
        cs[bc] = contrib;
    }
    __syncthreads();
    if (threadIdx.x == 0) {
        double s = 0.0;
        #pragma unroll
        for (int k = 0; k < 24; k++) s += cs[k];
        out[0] = (float)(s / (24.0 * (double)HW));
    }
}

extern "C" void kernel_launch(void* const* d_in, const int* in_sizes, int n_in,
                              void* d_out, int out_size) {
    const float* logits  = (const float*)d_in[0];
    const int*   targets = (const int*)d_in[1];

    dim3 g1(W / JT, BATCH);
    k1_colscan<<<g1, H>>>(targets);
    dim3 g2(RG, BATCH);
    k2_fused<<<g2, W>>>(logits);
    k3_final<<<1, 24 * 32>>>((float*)d_out);
}